// round 2
// baseline (speedup 1.0000x reference)
#include <cuda_runtime.h>

// ---------------- problem constants ----------------
#define EDGES   262144
#define NNODES  32768          // B*N = 8*4096
#define DD      128
#define FFH     512
#define LAYERS  2
#define KCAT    384            // 2*D + DE

// ---------------- scratch (device globals: no allocations allowed) ----------
__device__ float g_edge[EDGES * DD];    // current edge_attr
__device__ float g_h1  [EDGES * DD];    // hidden scratch
__device__ float g_h2  [EDGES * DD];    // hidden scratch
__device__ float g_agg [NNODES * DD];   // message aggregation
__device__ float g_ff  [NNODES * FFH];  // feedforward hidden
__device__ float g_tmp [NNODES * DD];   // ff output before LN
__device__ float g_ideg[NNODES];        // deg -> inv_deg (in place)

enum { A_DENSE = 0, A_CONCAT = 1 };
enum { EPI_RELU = 0, EPI_STORE = 1, EPI_ATOMIC = 2 };

// ---------------- tiled fp32 GEMM: C[M,BNtile] = A[M,K] @ W[K,N] ------------
// BM=128, BN=128, BK=16, 256 threads, 8x8 micro-tile per thread.
template <int AMODE, int EPI>
__global__ void __launch_bounds__(256, 2)
gemm_k(const float* __restrict__ A, int lda, int K,
       const float* __restrict__ nodes, const float* __restrict__ eattr,
       const int* __restrict__ src, const int* __restrict__ dst,
       const float* __restrict__ W, int ldw,
       const float* __restrict__ bias,
       float* __restrict__ out, int ldo)
{
    __shared__ float As[16][132];    // padded to kill STS bank conflicts
    __shared__ float Bs[16][128];
    __shared__ int   s_src[128], s_dst[128];

    const int tid = threadIdx.x;
    const int m0  = blockIdx.x * 128;
    const int n0  = blockIdx.y * 128;

    if (AMODE == A_CONCAT) {
        if (tid < 128) { s_src[tid] = src[m0 + tid]; s_dst[tid] = dst[m0 + tid]; }
        __syncthreads();
    }

    float acc[8][8];
#pragma unroll
    for (int i = 0; i < 8; i++)
#pragma unroll
        for (int j = 0; j < 8; j++) acc[i][j] = 0.f;

    const int tx = tid & 15;   // column group
    const int ty = tid >> 4;   // row group

    for (int k0 = 0; k0 < K; k0 += 16) {
        // ---- load A tile: 128 rows x 16 cols (512 float4, 2 per thread) ----
#pragma unroll
        for (int i = 0; i < 2; i++) {
            int idx = tid + i * 256;
            int row = idx >> 2;
            int kk  = (idx & 3) << 2;
            const float* ap;
            if (AMODE == A_CONCAT) {
                int kg = k0 + kk;
                if (kg < 128)      ap = nodes + (size_t)s_src[row] * 128 + kg;
                else if (kg < 256) ap = eattr + (size_t)(m0 + row) * 128 + (kg - 128);
                else               ap = nodes + (size_t)s_dst[row] * 128 + (kg - 256);
            } else {
                ap = A + (size_t)(m0 + row) * lda + k0 + kk;
            }
            float4 v = *(const float4*)ap;
            As[kk + 0][row] = v.x; As[kk + 1][row] = v.y;
            As[kk + 2][row] = v.z; As[kk + 3][row] = v.w;
        }
        // ---- load B tile: 16 rows x 128 cols ----
#pragma unroll
        for (int i = 0; i < 2; i++) {
            int idx = tid + i * 256;
            int kk  = idx >> 5;
            int nn  = (idx & 31) << 2;
            *(float4*)&Bs[kk][nn] =
                *(const float4*)(W + (size_t)(k0 + kk) * ldw + n0 + nn);
        }
        __syncthreads();
#pragma unroll
        for (int kk = 0; kk < 16; kk++) {
            float a[8], b[8];
            *(float4*)&a[0] = *(float4*)&As[kk][ty * 8];
            *(float4*)&a[4] = *(float4*)&As[kk][ty * 8 + 4];
            *(float4*)&b[0] = *(float4*)&Bs[kk][tx * 8];
            *(float4*)&b[4] = *(float4*)&Bs[kk][tx * 8 + 4];
#pragma unroll
            for (int i = 0; i < 8; i++)
#pragma unroll
                for (int j = 0; j < 8; j++) acc[i][j] += a[i] * b[j];
        }
        __syncthreads();
    }

    // ---- epilogue ----
    float bv[8];
#pragma unroll
    for (int j = 0; j < 8; j++) bv[j] = bias[n0 + tx * 8 + j];

#pragma unroll
    for (int i = 0; i < 8; i++) {
        int m = m0 + ty * 8 + i;
        if (EPI == EPI_ATOMIC) {
            int node = dst[m];
            float* dest = out + (size_t)node * 128 + tx * 8;
#pragma unroll
            for (int j = 0; j < 8; j++) atomicAdd(dest + j, acc[i][j] + bv[j]);
        } else {
            float r[8];
#pragma unroll
            for (int j = 0; j < 8; j++) {
                float v = acc[i][j] + bv[j];
                if (EPI == EPI_RELU) v = fmaxf(v, 0.f);
                r[j] = v;
            }
            float* op = out + (size_t)m * ldo + n0 + tx * 8;
            *(float4*)op       = *(float4*)&r[0];
            *(float4*)(op + 4) = *(float4*)&r[4];
        }
    }
}

// ---------------- LayerNorm (+residual, optional per-row scale) -------------
// io = LN(io + add * scale[row]) * g + b ; one warp per 128-wide row.
__global__ void ln_k(float* __restrict__ io, const float* __restrict__ add,
                     const float* __restrict__ scale,
                     const float* __restrict__ g, const float* __restrict__ b,
                     int rows)
{
    int row  = blockIdx.x * 8 + (threadIdx.x >> 5);
    int lane = threadIdx.x & 31;
    if (row >= rows) return;
    float s = scale ? scale[row] : 1.0f;

    float4 x = *(const float4*)(io  + (size_t)row * 128 + lane * 4);
    float4 a = *(const float4*)(add + (size_t)row * 128 + lane * 4);
    float v[4] = { x.x + a.x * s, x.y + a.y * s, x.z + a.z * s, x.w + a.w * s };

    float sum = v[0] + v[1] + v[2] + v[3];
#pragma unroll
    for (int off = 16; off > 0; off >>= 1) sum += __shfl_xor_sync(0xffffffffu, sum, off);
    float mean = sum * (1.0f / 128.0f);

    float sq = 0.f;
#pragma unroll
    for (int j = 0; j < 4; j++) { float d = v[j] - mean; sq += d * d; }
#pragma unroll
    for (int off = 16; off > 0; off >>= 1) sq += __shfl_xor_sync(0xffffffffu, sq, off);
    float inv = rsqrtf(sq * (1.0f / 128.0f) + 1e-5f);

    float4 gg = *(const float4*)(g + lane * 4);
    float4 bb = *(const float4*)(b + lane * 4);
    float4 o;
    o.x = (v[0] - mean) * inv * gg.x + bb.x;
    o.y = (v[1] - mean) * inv * gg.y + bb.y;
    o.z = (v[2] - mean) * inv * gg.z + bb.z;
    o.w = (v[3] - mean) * inv * gg.w + bb.w;
    *(float4*)(io + (size_t)row * 128 + lane * 4) = o;
}

// ---------------- small helpers ----------------
__global__ void copy_k(float4* __restrict__ d, const float4* __restrict__ s, int n4) {
    for (int i = blockIdx.x * blockDim.x + threadIdx.x; i < n4; i += gridDim.x * blockDim.x)
        d[i] = s[i];
}
__global__ void zero_k(float4* __restrict__ p, int n4) {
    for (int i = blockIdx.x * blockDim.x + threadIdx.x; i < n4; i += gridDim.x * blockDim.x)
        p[i] = make_float4(0.f, 0.f, 0.f, 0.f);
}
__global__ void deg_k(const int* __restrict__ dst, float* __restrict__ deg) {
    int e = blockIdx.x * blockDim.x + threadIdx.x;
    if (e < EDGES) atomicAdd(&deg[dst[e]], 1.0f);
}
__global__ void invdeg_k(float* __restrict__ deg) {
    int i = blockIdx.x * blockDim.x + threadIdx.x;
    if (i < NNODES) deg[i] = 1.0f / fmaxf(deg[i], 1.0f);
}

// ---------------- launch ----------------
extern "C" void kernel_launch(void* const* d_in, const int* in_sizes, int n_in,
                              void* d_out, int out_size)
{
    const float* x        = (const float*)d_in[0];
    const int*   eidx     = (const int*)  d_in[1];
    const float* eattr_in = (const float*)d_in[2];
    const float* msg_W0 = (const float*)d_in[3];
    const float* msg_b0 = (const float*)d_in[4];
    const float* msg_W1 = (const float*)d_in[5];
    const float* msg_b1 = (const float*)d_in[6];
    const float* msg_W2 = (const float*)d_in[7];
    const float* msg_b2 = (const float*)d_in[8];
    const float* n0g    = (const float*)d_in[9];
    const float* n0b    = (const float*)d_in[10];
    const float* ff_W0  = (const float*)d_in[11];
    const float* ff_b0  = (const float*)d_in[12];
    const float* ff_W1  = (const float*)d_in[13];
    const float* ff_b1  = (const float*)d_in[14];
    const float* n1g    = (const float*)d_in[15];
    const float* n1b    = (const float*)d_in[16];
    const float* eW0    = (const float*)d_in[17];
    const float* eb0    = (const float*)d_in[18];
    const float* eW1    = (const float*)d_in[19];
    const float* eb1    = (const float*)d_in[20];
    const float* eW2    = (const float*)d_in[21];
    const float* eb2    = (const float*)d_in[22];
    const float* eng    = (const float*)d_in[23];
    const float* enb    = (const float*)d_in[24];

    float* nodes = (float*)d_out;               // nodes live in d_out
    const int* src = eidx;
    const int* dst = eidx + EDGES;

    // Symbol addresses are process constants; resolve once, outside any
    // potential capture-sensitivity.
    static bool init = false;
    static float *edge, *h1, *h2, *agg, *ffb, *tmp, *ideg;
    if (!init) {
        cudaGetSymbolAddress((void**)&edge, g_edge);
        cudaGetSymbolAddress((void**)&h1,   g_h1);
        cudaGetSymbolAddress((void**)&h2,   g_h2);
        cudaGetSymbolAddress((void**)&agg,  g_agg);
        cudaGetSymbolAddress((void**)&ffb,  g_ff);
        cudaGetSymbolAddress((void**)&tmp,  g_tmp);
        cudaGetSymbolAddress((void**)&ideg, g_ideg);
        init = true;
    }

    // init: nodes <- x, edge <- edge_attr, inv_deg
    copy_k<<<2048, 256>>>((float4*)nodes, (const float4*)x, NNODES * DD / 4);
    copy_k<<<4096, 256>>>((float4*)edge, (const float4*)eattr_in, EDGES * DD / 4);
    zero_k<<<64, 256>>>((float4*)ideg, NNODES / 4);
    deg_k<<<EDGES / 256, 256>>>(dst, ideg);
    invdeg_k<<<NNODES / 256, 256>>>(ideg);

    const dim3 gE(EDGES / 128, 1), gN(NNODES / 128, 1), gF(NNODES / 128, FFH / 128);

    for (int l = 0; l < LAYERS; l++) {
        const float* mW0 = msg_W0 + (size_t)l * KCAT * DD;
        const float* mW1 = msg_W1 + (size_t)l * DD * DD;
        const float* mW2 = msg_W2 + (size_t)l * DD * DD;
        const float* fW0 = ff_W0  + (size_t)l * DD * FFH;
        const float* fW1 = ff_W1  + (size_t)l * FFH * DD;
        const float* xW0 = eW0    + (size_t)l * KCAT * DD;
        const float* xW1 = eW1    + (size_t)l * DD * DD;
        const float* xW2 = eW2    + (size_t)l * DD * DD;

        // --- message MLP + mean aggregation ---
        zero_k<<<4096, 256>>>((float4*)agg, NNODES * DD / 4);
        gemm_k<A_CONCAT, EPI_RELU><<<gE, 256>>>(nullptr, 0, KCAT, nodes, edge, src, dst,
                                                mW0, DD, msg_b0 + l * DD, h1, DD);
        gemm_k<A_DENSE, EPI_RELU><<<gE, 256>>>(h1, DD, DD, nullptr, nullptr, nullptr, nullptr,
                                               mW1, DD, msg_b1 + l * DD, h2, DD);
        gemm_k<A_DENSE, EPI_ATOMIC><<<gE, 256>>>(h2, DD, DD, nullptr, nullptr, nullptr, dst,
                                                 mW2, DD, msg_b2 + l * DD, agg, DD);
        ln_k<<<NNODES / 8, 256>>>(nodes, agg, ideg, n0g + l * DD, n0b + l * DD, NNODES);

        // --- feedforward ---
        gemm_k<A_DENSE, EPI_RELU><<<gF, 256>>>(nodes, DD, DD, nullptr, nullptr, nullptr, nullptr,
                                               fW0, FFH, ff_b0 + l * FFH, ffb, FFH);
        gemm_k<A_DENSE, EPI_STORE><<<gN, 256>>>(ffb, FFH, FFH, nullptr, nullptr, nullptr, nullptr,
                                                fW1, DD, ff_b1 + l * DD, tmp, DD);
        ln_k<<<NNODES / 8, 256>>>(nodes, tmp, nullptr, n1g + l * DD, n1b + l * DD, NNODES);

        // --- edge update MLP ---
        gemm_k<A_CONCAT, EPI_RELU><<<gE, 256>>>(nullptr, 0, KCAT, nodes, edge, src, dst,
                                                xW0, DD, eb0 + l * DD, h1, DD);
        gemm_k<A_DENSE, EPI_RELU><<<gE, 256>>>(h1, DD, DD, nullptr, nullptr, nullptr, nullptr,
                                               xW1, DD, eb1 + l * DD, h2, DD);
        gemm_k<A_DENSE, EPI_STORE><<<gE, 256>>>(h2, DD, DD, nullptr, nullptr, nullptr, nullptr,
                                                xW2, DD, eb2 + l * DD, h1, DD);
        ln_k<<<EDGES / 8, 256>>>(edge, h1, nullptr, eng + l * DD, enb + l * DD, EDGES);
    }
    // nodes (= d_out) already holds the final [B, N, D] result.
}

// round 4
// speedup vs baseline: 1.9302x; 1.9302x over previous
#include <cuda_runtime.h>
#include <cstdint>

// ---------------- problem constants ----------------
#define EDGES   262144
#define NNODES  32768
#define DD      128
#define FFH     512
#define LAYERS  2
#define KCAT    384

#define WT_PER_LAYER 294912   // floats of transposed weights per layer

// ---------------- scratch ----------------
__device__ float g_edge[EDGES * DD];
__device__ float g_h1  [EDGES * DD];
__device__ float g_h2  [EDGES * DD];
__device__ float g_agg [NNODES * DD];
__device__ float g_ff  [NNODES * FFH];
__device__ float g_ideg[NNODES];
__device__ float g_wt  [LAYERS * WT_PER_LAYER];

enum { A_DENSE = 0, A_CONCAT = 1 };
enum { EPI_RELU = 0, EPI_ATOMIC = 1, EPI_LNRES = 2 };

#define APITCH 36            // smem pitch (floats) for 32-k-wide operand tiles
static const int TILE_BYTES  = 128 * APITCH * 4;        // 18432 per operand
static const int STAGE_BYTES = 128 * 132 * 4;           // 67584
static const int DYN_SMEM    = STAGE_BYTES + 1024;      // union(A+B, stage)

// ---------------- device helpers ----------------
__device__ __forceinline__ float totf32(float x) {
    uint32_t t; asm("cvt.rna.tf32.f32 %0, %1;" : "=r"(t) : "f"(x));
    return __uint_as_float(t);
}
__device__ __forceinline__ void mma8(float* d, uint32_t a0, uint32_t a1,
                                     uint32_t a2, uint32_t a3,
                                     uint32_t b0, uint32_t b1) {
    asm volatile(
        "mma.sync.aligned.m16n8k8.row.col.f32.tf32.tf32.f32 "
        "{%0,%1,%2,%3}, {%4,%5,%6,%7}, {%8,%9}, {%0,%1,%2,%3};"
        : "+f"(d[0]), "+f"(d[1]), "+f"(d[2]), "+f"(d[3])
        : "r"(a0), "r"(a1), "r"(a2), "r"(a3), "r"(b0), "r"(b1));
}

// ---------------- tensor-core (mma.sync tf32) fused GEMM --------------------
// C[128 x 128] = A[M,K] @ Wt^T ; Wt is [N,K] K-major, tf32 + k-permuted.
template <int AMODE, int EPI>
__global__ void __launch_bounds__(256, 2)
gemm_tc(const float* __restrict__ A, int lda, int K,
        const float* __restrict__ nodes, const float* __restrict__ eattr,
        const int* __restrict__ srcI, const int* __restrict__ dstI,
        const float* __restrict__ Wt, const float* __restrict__ bias,
        float* __restrict__ out, int ldo,
        const float* __restrict__ resid,
        const float* __restrict__ lng, const float* __restrict__ lnb)
{
    extern __shared__ char dyn[];
    char*  base  = (char*)(((uintptr_t)dyn + 1023) & ~(uintptr_t)1023);
    float* As    = (float*)base;                    // [128][APITCH]
    float* Bs    = (float*)(base + TILE_BYTES);     // [128][APITCH]
    float* stage = (float*)base;                    // [128][132], after mma

    __shared__ int s_src[128], s_dst[128];

    const int tid  = threadIdx.x;
    const int wid  = tid >> 5;
    const int lane = tid & 31;
    const int g    = lane >> 2;      // 0..7
    const int r    = lane & 3;       // 0..3
    const int wm   = (wid & 3) * 32; // warp M base
    const int wn   = (wid >> 2) * 64;// warp N base
    const int m0   = blockIdx.x * 128;
    const int n0   = blockIdx.y * 128;

    if (AMODE == A_CONCAT && tid < 128) {
        s_src[tid] = srcI[m0 + tid];
        s_dst[tid] = dstI[m0 + tid];
    }
    if (AMODE == A_CONCAT) __syncthreads();

    float acc[2][8][4];
#pragma unroll
    for (int mt = 0; mt < 2; mt++)
#pragma unroll
        for (int nt = 0; nt < 8; nt++)
#pragma unroll
            for (int q = 0; q < 4; q++) acc[mt][nt][q] = 0.f;

    for (int k0 = 0; k0 < K; k0 += 32) {
        // ---- A tile: load fp32, convert tf32, store k-permuted ----
#pragma unroll
        for (int i = 0; i < 4; i++) {
            int f4  = tid + i * 256;          // 0..1023
            int row = f4 >> 3;
            int c   = f4 & 7;                 // float4 index within 32-float row
            const float* ap;
            if (AMODE == A_CONCAT) {
                if (k0 < 128)      ap = nodes + (size_t)s_src[row] * 128 + k0 + c * 4;
                else if (k0 < 256) ap = eattr + (size_t)(m0 + row) * 128 + (k0 - 128) + c * 4;
                else               ap = nodes + (size_t)s_dst[row] * 128 + (k0 - 256) + c * 4;
            } else {
                ap = A + (size_t)(m0 + row) * lda + k0 + c * 4;
            }
            float4 v = *(const float4*)ap;
            float* arow = As + row * APITCH;
            arow[ 0 + c] = totf32(v.x);       // p = e*8 + c
            arow[ 8 + c] = totf32(v.y);
            arow[16 + c] = totf32(v.z);
            arow[24 + c] = totf32(v.w);
            // ---- B tile: already tf32 + permuted in global; straight copy ----
            *(float4*)(Bs + row * APITCH + c * 4) =
                *(const float4*)(Wt + (size_t)(n0 + row) * K + k0 + c * 4);
        }
        __syncthreads();

        // ---- 4 k-steps of m16n8k8 ----
#pragma unroll
        for (int s = 0; s < 4; s++) {
            uint2 al[2], ah[2];
#pragma unroll
            for (int mt = 0; mt < 2; mt++) {
                const float* p0 = As + (wm + mt * 16 + g) * APITCH + r * 8 + 2 * s;
                al[mt] = *(const uint2*)p0;                       // a0, a2
                ah[mt] = *(const uint2*)(p0 + 8 * APITCH);        // a1, a3
            }
            uint2 bf[8];
#pragma unroll
            for (int nt = 0; nt < 8; nt++)
                bf[nt] = *(const uint2*)(Bs + (wn + nt * 8 + g) * APITCH + r * 8 + 2 * s);
#pragma unroll
            for (int mt = 0; mt < 2; mt++)
#pragma unroll
                for (int nt = 0; nt < 8; nt++)
                    mma8(acc[mt][nt], al[mt].x, ah[mt].x, al[mt].y, ah[mt].y,
                         bf[nt].x, bf[nt].y);
        }
        __syncthreads();
    }

    // ---- stage accumulators into smem (pitch 132) ----
#pragma unroll
    for (int mt = 0; mt < 2; mt++) {
        int rw0 = wm + mt * 16 + g;
#pragma unroll
        for (int nt = 0; nt < 8; nt++) {
            int col = wn + nt * 8 + 2 * r;
            *(float2*)(stage + rw0 * 132 + col)       = make_float2(acc[mt][nt][0], acc[mt][nt][1]);
            *(float2*)(stage + (rw0 + 8) * 132 + col) = make_float2(acc[mt][nt][2], acc[mt][nt][3]);
        }
    }
    __syncthreads();

    // ---- epilogue from stage ----
    if (EPI == EPI_RELU) {
#pragma unroll
        for (int it = 0; it < 16; it++) {
            int f4  = it * 256 + tid;
            int row = f4 >> 5;
            int c4  = f4 & 31;
            float4 v = *(float4*)(stage + row * 132 + c4 * 4);
            float4 bb = *(const float4*)(bias + n0 + c4 * 4);
            v.x = fmaxf(v.x + bb.x, 0.f); v.y = fmaxf(v.y + bb.y, 0.f);
            v.z = fmaxf(v.z + bb.z, 0.f); v.w = fmaxf(v.w + bb.w, 0.f);
            *(float4*)(out + (size_t)(m0 + row) * ldo + n0 + c4 * 4) = v;
        }
    } else if (EPI == EPI_ATOMIC) {
#pragma unroll
        for (int it = 0; it < 16; it++) {
            int f4  = it * 256 + tid;
            int row = f4 >> 5;
            int c4  = f4 & 31;
            float4 v = *(float4*)(stage + row * 132 + c4 * 4);
            float4 bb = *(const float4*)(bias + c4 * 4);
            float* dbase = out + (size_t)dstI[m0 + row] * 128 + c4 * 4;
            asm volatile("red.global.add.v4.f32 [%0], {%1,%2,%3,%4};"
                         :: "l"(dbase), "f"(v.x + bb.x), "f"(v.y + bb.y),
                            "f"(v.z + bb.z), "f"(v.w + bb.w) : "memory");
        }
    } else {  // EPI_LNRES: residual + bias + LayerNorm, full 128-wide rows
        float4 gg = *(const float4*)(lng + lane * 4);
        float4 bbn = *(const float4*)(lnb + lane * 4);
        float4 bz = *(const float4*)(bias + lane * 4);
        for (int rr = wid; rr < 128; rr += 8) {
            float4 res = *(const float4*)(resid + (size_t)(m0 + rr) * 128 + lane * 4);
            float4 d   = *(float4*)(stage + rr * 132 + lane * 4);
            float v0 = res.x + d.x + bz.x, v1 = res.y + d.y + bz.y;
            float v2 = res.z + d.z + bz.z, v3 = res.w + d.w + bz.w;
            float sum = v0 + v1 + v2 + v3;
#pragma unroll
            for (int off = 16; off > 0; off >>= 1)
                sum += __shfl_xor_sync(0xffffffffu, sum, off);
            float mean = sum * (1.0f / 128.0f);
            float d0 = v0 - mean, d1 = v1 - mean, d2 = v2 - mean, d3 = v3 - mean;
            float sq = d0 * d0 + d1 * d1 + d2 * d2 + d3 * d3;
#pragma unroll
            for (int off = 16; off > 0; off >>= 1)
                sq += __shfl_xor_sync(0xffffffffu, sq, off);
            float inv = rsqrtf(sq * (1.0f / 128.0f) + 1e-5f);
            float4 o;
            o.x = d0 * inv * gg.x + bbn.x;
            o.y = d1 * inv * gg.y + bbn.y;
            o.z = d2 * inv * gg.z + bbn.z;
            o.w = d3 * inv * gg.w + bbn.w;
            *(float4*)(out + (size_t)(m0 + rr) * 128 + lane * 4) = o;
        }
    }
}

// ---------------- standalone LayerNorm (node norm0 after aggregation) -------
__global__ void ln_k(float* __restrict__ io, const float* __restrict__ add,
                     const float* __restrict__ scale,
                     const float* __restrict__ g, const float* __restrict__ b,
                     int rows)
{
    int row  = blockIdx.x * 8 + (threadIdx.x >> 5);
    int lane = threadIdx.x & 31;
    if (row >= rows) return;
    float s = scale ? scale[row] : 1.0f;

    float4 x = *(const float4*)(io  + (size_t)row * 128 + lane * 4);
    float4 a = *(const float4*)(add + (size_t)row * 128 + lane * 4);
    float v[4] = { x.x + a.x * s, x.y + a.y * s, x.z + a.z * s, x.w + a.w * s };

    float sum = v[0] + v[1] + v[2] + v[3];
#pragma unroll
    for (int off = 16; off > 0; off >>= 1) sum += __shfl_xor_sync(0xffffffffu, sum, off);
    float mean = sum * (1.0f / 128.0f);
    float sq = 0.f;
#pragma unroll
    for (int j = 0; j < 4; j++) { float d = v[j] - mean; sq += d * d; }
#pragma unroll
    for (int off = 16; off > 0; off >>= 1) sq += __shfl_xor_sync(0xffffffffu, sq, off);
    float inv = rsqrtf(sq * (1.0f / 128.0f) + 1e-5f);

    float4 gg = *(const float4*)(g + lane * 4);
    float4 bb = *(const float4*)(b + lane * 4);
    float4 o;
    o.x = (v[0] - mean) * inv * gg.x + bb.x;
    o.y = (v[1] - mean) * inv * gg.y + bb.y;
    o.z = (v[2] - mean) * inv * gg.z + bb.z;
    o.w = (v[3] - mean) * inv * gg.w + bb.w;
    *(float4*)(io + (size_t)row * 128 + lane * 4) = o;
}

// ---------------- weight transpose + tf32 convert + k-permute ----------------
// dst[n*K + c*32 + p] = tf32(src[k*N + n]), k = c*32 + (p&7)*4 + (p>>3)
__global__ void wt_k(float* __restrict__ dst, const float* __restrict__ src, int K, int N) {
    int i = blockIdx.x * blockDim.x + threadIdx.x;
    if (i >= K * N) return;
    int n = i / K, rem = i - n * K;
    int c = rem >> 5, p = rem & 31;
    int k = c * 32 + ((p & 7) << 2) + (p >> 3);
    dst[i] = totf32(src[(size_t)k * N + n]);
}
__global__ void copy_k(float4* __restrict__ d, const float4* __restrict__ s, int n4) {
    for (int i = blockIdx.x * blockDim.x + threadIdx.x; i < n4; i += gridDim.x * blockDim.x)
        d[i] = s[i];
}
__global__ void zero_k(float4* __restrict__ p, int n4) {
    for (int i = blockIdx.x * blockDim.x + threadIdx.x; i < n4; i += gridDim.x * blockDim.x)
        p[i] = make_float4(0.f, 0.f, 0.f, 0.f);
}
__global__ void deg_k(const int* __restrict__ dst, float* __restrict__ deg) {
    int e = blockIdx.x * blockDim.x + threadIdx.x;
    if (e < EDGES) atomicAdd(&deg[dst[e]], 1.0f);
}
__global__ void invdeg_k(float* __restrict__ deg) {
    int i = blockIdx.x * blockDim.x + threadIdx.x;
    if (i < NNODES) deg[i] = 1.0f / fmaxf(deg[i], 1.0f);
}

// ---------------- launch ----------------
extern "C" void kernel_launch(void* const* d_in, const int* in_sizes, int n_in,
                              void* d_out, int out_size)
{
    const float* x        = (const float*)d_in[0];
    const int*   eidx     = (const int*)  d_in[1];
    const float* eattr_in = (const float*)d_in[2];
    const float* msg_W0 = (const float*)d_in[3];
    const float* msg_b0 = (const float*)d_in[4];
    const float* msg_W1 = (const float*)d_in[5];
    const float* msg_b1 = (const float*)d_in[6];
    const float* msg_W2 = (const float*)d_in[7];
    const float* msg_b2 = (const float*)d_in[8];
    const float* n0g    = (const float*)d_in[9];
    const float* n0b    = (const float*)d_in[10];
    const float* ff_W0  = (const float*)d_in[11];
    const float* ff_b0  = (const float*)d_in[12];
    const float* ff_W1  = (const float*)d_in[13];
    const float* ff_b1  = (const float*)d_in[14];
    const float* n1g    = (const float*)d_in[15];
    const float* n1b    = (const float*)d_in[16];
    const float* eW0    = (const float*)d_in[17];
    const float* eb0    = (const float*)d_in[18];
    const float* eW1    = (const float*)d_in[19];
    const float* eb1    = (const float*)d_in[20];
    const float* eW2    = (const float*)d_in[21];
    const float* eb2    = (const float*)d_in[22];
    const float* eng    = (const float*)d_in[23];
    const float* enb    = (const float*)d_in[24];

    float* nodes = (float*)d_out;
    const int* src = eidx;
    const int* dst = eidx + EDGES;

    static bool init = false;
    static float *edge, *h1, *h2, *agg, *ffb, *ideg, *wt;
    if (!init) {
        cudaGetSymbolAddress((void**)&edge, g_edge);
        cudaGetSymbolAddress((void**)&h1,   g_h1);
        cudaGetSymbolAddress((void**)&h2,   g_h2);
        cudaGetSymbolAddress((void**)&agg,  g_agg);
        cudaGetSymbolAddress((void**)&ffb,  g_ff);
        cudaGetSymbolAddress((void**)&ideg, g_ideg);
        cudaGetSymbolAddress((void**)&wt,   g_wt);
        cudaFuncSetAttribute(gemm_tc<A_CONCAT, EPI_RELU>,
                             cudaFuncAttributeMaxDynamicSharedMemorySize, DYN_SMEM);
        cudaFuncSetAttribute(gemm_tc<A_DENSE, EPI_RELU>,
                             cudaFuncAttributeMaxDynamicSharedMemorySize, DYN_SMEM);
        cudaFuncSetAttribute(gemm_tc<A_DENSE, EPI_ATOMIC>,
                             cudaFuncAttributeMaxDynamicSharedMemorySize, DYN_SMEM);
        cudaFuncSetAttribute(gemm_tc<A_DENSE, EPI_LNRES>,
                             cudaFuncAttributeMaxDynamicSharedMemorySize, DYN_SMEM);
        init = true;
    }

    // init: nodes <- x, edge <- edge_attr, inv_deg
    copy_k<<<2048, 256>>>((float4*)nodes, (const float4*)x, NNODES * DD / 4);
    copy_k<<<4096, 256>>>((float4*)edge, (const float4*)eattr_in, EDGES * DD / 4);
    zero_k<<<64, 256>>>((float4*)ideg, NNODES / 4);
    deg_k<<<EDGES / 256, 256>>>(dst, ideg);
    invdeg_k<<<NNODES / 256, 256>>>(ideg);

    // transpose + tf32 + permute weights into [N,K] scratch
    const int O_MW0 = 0, O_MW1 = 49152, O_MW2 = 65536, O_FW0 = 81920,
              O_FW1 = 147456, O_EW0 = 212992, O_EW1 = 262144, O_EW2 = 278528;
    for (int l = 0; l < LAYERS; l++) {
        float* wl = wt + (size_t)l * WT_PER_LAYER;
        wt_k<<<(KCAT * DD + 255) / 256, 256>>>(wl + O_MW0, msg_W0 + (size_t)l * KCAT * DD, KCAT, DD);
        wt_k<<<(DD * DD + 255) / 256, 256>>>(wl + O_MW1, msg_W1 + (size_t)l * DD * DD, DD, DD);
        wt_k<<<(DD * DD + 255) / 256, 256>>>(wl + O_MW2, msg_W2 + (size_t)l * DD * DD, DD, DD);
        wt_k<<<(DD * FFH + 255) / 256, 256>>>(wl + O_FW0, ff_W0 + (size_t)l * DD * FFH, DD, FFH);
        wt_k<<<(FFH * DD + 255) / 256, 256>>>(wl + O_FW1, ff_W1 + (size_t)l * FFH * DD, FFH, DD);
        wt_k<<<(KCAT * DD + 255) / 256, 256>>>(wl + O_EW0, eW0 + (size_t)l * KCAT * DD, KCAT, DD);
        wt_k<<<(DD * DD + 255) / 256, 256>>>(wl + O_EW1, eW1 + (size_t)l * DD * DD, DD, DD);
        wt_k<<<(DD * DD + 255) / 256, 256>>>(wl + O_EW2, eW2 + (size_t)l * DD * DD, DD, DD);
    }

    const dim3 gE(EDGES / 128, 1), gN(NNODES / 128, 1), gF(NNODES / 128, FFH / 128);

    for (int l = 0; l < LAYERS; l++) {
        float* wl = wt + (size_t)l * WT_PER_LAYER;

        // --- message MLP + mean aggregation ---
        zero_k<<<4096, 256>>>((float4*)agg, NNODES * DD / 4);
        gemm_tc<A_CONCAT, EPI_RELU><<<gE, 256, DYN_SMEM>>>(
            nullptr, 0, KCAT, nodes, edge, src, dst, wl + O_MW0,
            msg_b0 + l * DD, h1, DD, nullptr, nullptr, nullptr);
        gemm_tc<A_DENSE, EPI_RELU><<<gE, 256, DYN_SMEM>>>(
            h1, DD, DD, nullptr, nullptr, nullptr, nullptr, wl + O_MW1,
            msg_b1 + l * DD, h2, DD, nullptr, nullptr, nullptr);
        gemm_tc<A_DENSE, EPI_ATOMIC><<<gE, 256, DYN_SMEM>>>(
            h2, DD, DD, nullptr, nullptr, nullptr, dst, wl + O_MW2,
            msg_b2 + l * DD, agg, DD, nullptr, nullptr, nullptr);
        ln_k<<<NNODES / 8, 256>>>(nodes, agg, ideg, n0g + l * DD, n0b + l * DD, NNODES);

        // --- feedforward (norm1 fused into FF2 epilogue) ---
        gemm_tc<A_DENSE, EPI_RELU><<<gF, 256, DYN_SMEM>>>(
            nodes, DD, DD, nullptr, nullptr, nullptr, nullptr, wl + O_FW0,
            ff_b0 + l * FFH, ffb, FFH, nullptr, nullptr, nullptr);
        gemm_tc<A_DENSE, EPI_LNRES><<<gN, 256, DYN_SMEM>>>(
            ffb, FFH, FFH, nullptr, nullptr, nullptr, nullptr, wl + O_FW1,
            ff_b1 + l * DD, nodes, DD, nodes, n1g + l * DD, n1b + l * DD);

        // --- edge update MLP (enorm fused into E3 epilogue) ---
        gemm_tc<A_CONCAT, EPI_RELU><<<gE, 256, DYN_SMEM>>>(
            nullptr, 0, KCAT, nodes, edge, src, dst, wl + O_EW0,
            eb0 + l * DD, h1, DD, nullptr, nullptr, nullptr);
        gemm_tc<A_DENSE, EPI_RELU><<<gE, 256, DYN_SMEM>>>(
            h1, DD, DD, nullptr, nullptr, nullptr, nullptr, wl + O_EW1,
            eb1 + l * DD, h2, DD, nullptr, nullptr, nullptr);
        gemm_tc<A_DENSE, EPI_LNRES><<<gE, 256, DYN_SMEM>>>(
            h2, DD, DD, nullptr, nullptr, nullptr, nullptr, wl + O_EW2,
            eb2 + l * DD, edge, DD, edge, eng + l * DD, enb + l * DD);
    }
    // nodes (= d_out) holds the final [B, N, D] result.
}

// round 5
// speedup vs baseline: 2.0889x; 1.0823x over previous
#include <cuda_runtime.h>
#include <cstdint>

// ---------------- problem constants ----------------
#define EDGES   262144
#define NNODES  32768
#define DD      128
#define FFH     512
#define LAYERS  2
#define KCAT    384

#define WT_PER_LAYER 294912

// ---------------- scratch ----------------
__device__ float g_edge[EDGES * DD];
__device__ float g_agg [NNODES * DD];
__device__ float g_ff  [NNODES * FFH];
__device__ float g_ideg[NNODES];
__device__ float g_wt  [LAYERS * WT_PER_LAYER];

enum { A_DENSE = 0 };
enum { EPI_RELU = 0, EPI_ATOMIC = 1, EPI_LNRES = 2 };

#define APITCH 36              // pitch (floats) of one 32-k operand chunk
#define HROW   146             // row stride (floats) of 4-chunk activation buf
static const int TILE_BYTES = 128 * APITCH * 4;     // 18432
static const int DYN_GEMM   = 128 * 132 * 4 + 1024; // gemm_tc stage
static const int HA_BYTES   = 128 * HROW * 4;       // 74752
static const int DYN_MLP    = HA_BYTES + 2 * TILE_BYTES + 1024;  // 112640

// ---------------- device helpers ----------------
__device__ __forceinline__ float totf32(float x) {
    uint32_t t; asm("cvt.rna.tf32.f32 %0, %1;" : "=r"(t) : "f"(x));
    return __uint_as_float(t);
}
__device__ __forceinline__ void mma8(float* d, uint32_t a0, uint32_t a1,
                                     uint32_t a2, uint32_t a3,
                                     uint32_t b0, uint32_t b1) {
    asm volatile(
        "mma.sync.aligned.m16n8k8.row.col.f32.tf32.tf32.f32 "
        "{%0,%1,%2,%3}, {%4,%5,%6,%7}, {%8,%9}, {%0,%1,%2,%3};"
        : "+f"(d[0]), "+f"(d[1]), "+f"(d[2]), "+f"(d[3])
        : "r"(a0), "r"(a1), "r"(a2), "r"(a3), "r"(b0), "r"(b1));
}
// one 32-k chunk of m16n8k8 MMAs; A at Abase (pitch apitch), B at Bs (pitch 36)
__device__ __forceinline__ void chunk_mma(const float* Abase, int apitch,
                                          const float* Bs,
                                          int wm, int wn, int g, int r,
                                          float acc[2][8][4]) {
#pragma unroll
    for (int s = 0; s < 4; s++) {
        uint2 al[2], ah[2];
#pragma unroll
        for (int mt = 0; mt < 2; mt++) {
            const float* p0 = Abase + (wm + mt * 16 + g) * apitch + r * 8 + 2 * s;
            al[mt] = *(const uint2*)p0;
            ah[mt] = *(const uint2*)(p0 + 8 * apitch);
        }
        uint2 bf[8];
#pragma unroll
        for (int nt = 0; nt < 8; nt++)
            bf[nt] = *(const uint2*)(Bs + (wn + nt * 8 + g) * APITCH + r * 8 + 2 * s);
#pragma unroll
        for (int mt = 0; mt < 2; mt++)
#pragma unroll
            for (int nt = 0; nt < 8; nt++)
                mma8(acc[mt][nt], al[mt].x, ah[mt].x, al[mt].y, ah[mt].y,
                     bf[nt].x, bf[nt].y);
    }
}
// accumulators -> activation buffer (bias + relu + tf32, k-permuted); zero acc
__device__ __forceinline__ void wb_relu(float* HA, float acc[2][8][4],
                                        const float* bias,
                                        int wm, int wn, int g, int r) {
#pragma unroll
    for (int mt = 0; mt < 2; mt++)
#pragma unroll
        for (int q = 0; q < 4; q++) {
            int row = wm + mt * 16 + g + ((q & 2) ? 8 : 0);
#pragma unroll
            for (int nt = 0; nt < 8; nt++) {
                int col = wn + nt * 8 + 2 * r + (q & 1);
                float v = fmaxf(acc[mt][nt][q] + __ldg(bias + col), 0.f);
                int kk = col & 31;
                HA[row * HROW + (col >> 5) * APITCH + (kk & 3) * 8 + (kk >> 2)]
                    = totf32(v);
                acc[mt][nt][q] = 0.f;
            }
        }
}

// ---------------- fused 3-linear MLP over edges ----------------
// out = stage2( relu(relu(concat@W0+b0)@W1+b1) @ W2 )  with EPI epilogue
template <int EPI>
__global__ void __launch_bounds__(256, 2)
mlp3_tc(const float* __restrict__ nodes, const float* __restrict__ eattr,
        const int* __restrict__ srcI, const int* __restrict__ dstI,
        const float* __restrict__ W0t, const float* __restrict__ b0,
        const float* __restrict__ W1t, const float* __restrict__ b1,
        const float* __restrict__ W2t, const float* __restrict__ b2,
        float* __restrict__ out, const float* __restrict__ resid,
        const float* __restrict__ lng, const float* __restrict__ lnb)
{
    extern __shared__ char dyn[];
    char*  basep = (char*)(((uintptr_t)dyn + 1023) & ~(uintptr_t)1023);
    float* HA    = (float*)basep;                       // [128][HROW]
    float* Bs    = (float*)(basep + HA_BYTES);          // [128][36]
    float* As    = (float*)(basep + HA_BYTES + TILE_BYTES);
    float* stage = HA;                                  // reuse, pitch 132

    __shared__ int s_src[128], s_dst[128];

    const int tid  = threadIdx.x;
    const int wid  = tid >> 5;
    const int lane = tid & 31;
    const int g    = lane >> 2;
    const int r    = lane & 3;
    const int wm   = (wid & 3) * 32;
    const int wn   = (wid >> 2) * 64;
    const int m0   = blockIdx.x * 128;

    if (tid < 128) { s_src[tid] = srcI[m0 + tid]; s_dst[tid] = dstI[m0 + tid]; }
    __syncthreads();

    float acc[2][8][4];
#pragma unroll
    for (int mt = 0; mt < 2; mt++)
#pragma unroll
        for (int nt = 0; nt < 8; nt++)
#pragma unroll
            for (int q = 0; q < 4; q++) acc[mt][nt][q] = 0.f;

    // ---- stage 0: K = 384 (gathered concat) ----
    for (int c = 0; c < 12; c++) {
        int k0 = c * 32;
#pragma unroll
        for (int i = 0; i < 4; i++) {
            int f4  = tid + i * 256;
            int row = f4 >> 3;
            int cc  = f4 & 7;
            const float* ap;
            if (k0 < 128)      ap = nodes + (size_t)s_src[row] * 128 + k0 + cc * 4;
            else if (k0 < 256) ap = eattr + (size_t)(m0 + row) * 128 + (k0 - 128) + cc * 4;
            else               ap = nodes + (size_t)s_dst[row] * 128 + (k0 - 256) + cc * 4;
            float4 v = *(const float4*)ap;
            float* arow = As + row * APITCH;
            arow[ 0 + cc] = totf32(v.x);
            arow[ 8 + cc] = totf32(v.y);
            arow[16 + cc] = totf32(v.z);
            arow[24 + cc] = totf32(v.w);
            *(float4*)(Bs + row * APITCH + cc * 4) =
                *(const float4*)(W0t + (size_t)row * KCAT + k0 + cc * 4);
        }
        __syncthreads();
        chunk_mma(As, APITCH, Bs, wm, wn, g, r, acc);
        __syncthreads();
    }
    wb_relu(HA, acc, b0, wm, wn, g, r);
    __syncthreads();

    // ---- stage 1: K = 128, A from HA ----
    for (int c = 0; c < 4; c++) {
#pragma unroll
        for (int i = 0; i < 4; i++) {
            int f4 = tid + i * 256;
            int row = f4 >> 3, cc = f4 & 7;
            *(float4*)(Bs + row * APITCH + cc * 4) =
                *(const float4*)(W1t + (size_t)row * 128 + c * 32 + cc * 4);
        }
        __syncthreads();
        chunk_mma(HA + c * APITCH, HROW, Bs, wm, wn, g, r, acc);
        __syncthreads();
    }
    wb_relu(HA, acc, b1, wm, wn, g, r);
    __syncthreads();

    // ---- stage 2: K = 128 ----
    for (int c = 0; c < 4; c++) {
#pragma unroll
        for (int i = 0; i < 4; i++) {
            int f4 = tid + i * 256;
            int row = f4 >> 3, cc = f4 & 7;
            *(float4*)(Bs + row * APITCH + cc * 4) =
                *(const float4*)(W2t + (size_t)row * 128 + c * 32 + cc * 4);
        }
        __syncthreads();
        chunk_mma(HA + c * APITCH, HROW, Bs, wm, wn, g, r, acc);
        __syncthreads();
    }

    // ---- epilogue ----
    if (EPI == EPI_ATOMIC) {
        // restage acc + b2, then coalesced vector-red scatter to dst nodes
#pragma unroll
        for (int mt = 0; mt < 2; mt++)
#pragma unroll
            for (int q = 0; q < 4; q++) {
                int row = wm + mt * 16 + g + ((q & 2) ? 8 : 0);
#pragma unroll
                for (int nt = 0; nt < 8; nt++) {
                    int col = wn + nt * 8 + 2 * r + (q & 1);
                    stage[row * 132 + col] = acc[mt][nt][q] + __ldg(b2 + col);
                }
            }
        __syncthreads();
#pragma unroll
        for (int it = 0; it < 16; it++) {
            int f4  = it * 256 + tid;
            int row = f4 >> 5;
            int c4  = f4 & 31;
            float4 v = *(float4*)(stage + row * 132 + c4 * 4);
            float* dbase = out + (size_t)s_dst[row] * 128 + c4 * 4;
            asm volatile("red.global.add.v4.f32 [%0], {%1,%2,%3,%4};"
                         :: "l"(dbase), "f"(v.x), "f"(v.y), "f"(v.z), "f"(v.w)
                         : "memory");
        }
    } else {  // EPI_LNRES: out = LN(resid + acc + b2)
#pragma unroll
        for (int mt = 0; mt < 2; mt++)
#pragma unroll
            for (int q = 0; q < 4; q++) {
                int row = wm + mt * 16 + g + ((q & 2) ? 8 : 0);
#pragma unroll
                for (int nt = 0; nt < 8; nt++) {
                    int col = wn + nt * 8 + 2 * r + (q & 1);
                    stage[row * 132 + col] = acc[mt][nt][q];
                }
            }
        __syncthreads();
        float4 gg  = *(const float4*)(lng + lane * 4);
        float4 bbn = *(const float4*)(lnb + lane * 4);
        float4 bz  = *(const float4*)(b2 + lane * 4);
        for (int rr = wid; rr < 128; rr += 8) {
            float4 res = *(const float4*)(resid + (size_t)(m0 + rr) * 128 + lane * 4);
            float4 d   = *(float4*)(stage + rr * 132 + lane * 4);
            float v0 = res.x + d.x + bz.x, v1 = res.y + d.y + bz.y;
            float v2 = res.z + d.z + bz.z, v3 = res.w + d.w + bz.w;
            float sum = v0 + v1 + v2 + v3;
#pragma unroll
            for (int off = 16; off > 0; off >>= 1)
                sum += __shfl_xor_sync(0xffffffffu, sum, off);
            float mean = sum * (1.0f / 128.0f);
            float d0 = v0 - mean, d1 = v1 - mean, d2 = v2 - mean, d3 = v3 - mean;
            float sq = d0 * d0 + d1 * d1 + d2 * d2 + d3 * d3;
#pragma unroll
            for (int off = 16; off > 0; off >>= 1)
                sq += __shfl_xor_sync(0xffffffffu, sq, off);
            float inv = rsqrtf(sq * (1.0f / 128.0f) + 1e-5f);
            float4 o;
            o.x = d0 * inv * gg.x + bbn.x;
            o.y = d1 * inv * gg.y + bbn.y;
            o.z = d2 * inv * gg.z + bbn.z;
            o.w = d3 * inv * gg.w + bbn.w;
            *(float4*)(out + (size_t)(m0 + rr) * 128 + lane * 4) = o;
        }
    }
}

// ---------------- dense GEMM (feedforward) ----------------
template <int EPI>
__global__ void __launch_bounds__(256, 2)
gemm_tc(const float* __restrict__ A, int lda, int K,
        const float* __restrict__ Wt, const float* __restrict__ bias,
        float* __restrict__ out, int ldo,
        const float* __restrict__ resid,
        const float* __restrict__ lng, const float* __restrict__ lnb)
{
    extern __shared__ char dyn[];
    char*  base  = (char*)(((uintptr_t)dyn + 1023) & ~(uintptr_t)1023);
    float* As    = (float*)base;
    float* Bs    = (float*)(base + TILE_BYTES);
    float* stage = (float*)base;

    const int tid  = threadIdx.x;
    const int wid  = tid >> 5;
    const int lane = tid & 31;
    const int g    = lane >> 2;
    const int r    = lane & 3;
    const int wm   = (wid & 3) * 32;
    const int wn   = (wid >> 2) * 64;
    const int m0   = blockIdx.x * 128;
    const int n0   = blockIdx.y * 128;

    float acc[2][8][4];
#pragma unroll
    for (int mt = 0; mt < 2; mt++)
#pragma unroll
        for (int nt = 0; nt < 8; nt++)
#pragma unroll
            for (int q = 0; q < 4; q++) acc[mt][nt][q] = 0.f;

    for (int k0 = 0; k0 < K; k0 += 32) {
#pragma unroll
        for (int i = 0; i < 4; i++) {
            int f4  = tid + i * 256;
            int row = f4 >> 3;
            int c   = f4 & 7;
            float4 v = *(const float4*)(A + (size_t)(m0 + row) * lda + k0 + c * 4);
            float* arow = As + row * APITCH;
            arow[ 0 + c] = totf32(v.x);
            arow[ 8 + c] = totf32(v.y);
            arow[16 + c] = totf32(v.z);
            arow[24 + c] = totf32(v.w);
            *(float4*)(Bs + row * APITCH + c * 4) =
                *(const float4*)(Wt + (size_t)(n0 + row) * K + k0 + c * 4);
        }
        __syncthreads();
        chunk_mma(As, APITCH, Bs, wm, wn, g, r, acc);
        __syncthreads();
    }

#pragma unroll
    for (int mt = 0; mt < 2; mt++) {
        int rw0 = wm + mt * 16 + g;
#pragma unroll
        for (int nt = 0; nt < 8; nt++) {
            int col = wn + nt * 8 + 2 * r;
            *(float2*)(stage + rw0 * 132 + col)       = make_float2(acc[mt][nt][0], acc[mt][nt][1]);
            *(float2*)(stage + (rw0 + 8) * 132 + col) = make_float2(acc[mt][nt][2], acc[mt][nt][3]);
        }
    }
    __syncthreads();

    if (EPI == EPI_RELU) {
#pragma unroll
        for (int it = 0; it < 16; it++) {
            int f4  = it * 256 + tid;
            int row = f4 >> 5;
            int c4  = f4 & 31;
            float4 v  = *(float4*)(stage + row * 132 + c4 * 4);
            float4 bb = *(const float4*)(bias + n0 + c4 * 4);
            v.x = fmaxf(v.x + bb.x, 0.f); v.y = fmaxf(v.y + bb.y, 0.f);
            v.z = fmaxf(v.z + bb.z, 0.f); v.w = fmaxf(v.w + bb.w, 0.f);
            *(float4*)(out + (size_t)(m0 + row) * ldo + n0 + c4 * 4) = v;
        }
    } else {  // EPI_LNRES
        float4 gg  = *(const float4*)(lng + lane * 4);
        float4 bbn = *(const float4*)(lnb + lane * 4);
        float4 bz  = *(const float4*)(bias + lane * 4);
        for (int rr = wid; rr < 128; rr += 8) {
            float4 res = *(const float4*)(resid + (size_t)(m0 + rr) * 128 + lane * 4);
            float4 d   = *(float4*)(stage + rr * 132 + lane * 4);
            float v0 = res.x + d.x + bz.x, v1 = res.y + d.y + bz.y;
            float v2 = res.z + d.z + bz.z, v3 = res.w + d.w + bz.w;
            float sum = v0 + v1 + v2 + v3;
#pragma unroll
            for (int off = 16; off > 0; off >>= 1)
                sum += __shfl_xor_sync(0xffffffffu, sum, off);
            float mean = sum * (1.0f / 128.0f);
            float d0 = v0 - mean, d1 = v1 - mean, d2 = v2 - mean, d3 = v3 - mean;
            float sq = d0 * d0 + d1 * d1 + d2 * d2 + d3 * d3;
#pragma unroll
            for (int off = 16; off > 0; off >>= 1)
                sq += __shfl_xor_sync(0xffffffffu, sq, off);
            float inv = rsqrtf(sq * (1.0f / 128.0f) + 1e-5f);
            float4 o;
            o.x = d0 * inv * gg.x + bbn.x;
            o.y = d1 * inv * gg.y + bbn.y;
            o.z = d2 * inv * gg.z + bbn.z;
            o.w = d3 * inv * gg.w + bbn.w;
            *(float4*)(out + (size_t)(m0 + rr) * 128 + lane * 4) = o;
        }
    }
}

// ---------------- standalone LayerNorm (norm0) ----------------
__global__ void ln_k(float* __restrict__ io, const float* __restrict__ add,
                     const float* __restrict__ scale,
                     const float* __restrict__ g, const float* __restrict__ b,
                     int rows)
{
    int row  = blockIdx.x * 8 + (threadIdx.x >> 5);
    int lane = threadIdx.x & 31;
    if (row >= rows) return;
    float s = scale ? scale[row] : 1.0f;

    float4 x = *(const float4*)(io  + (size_t)row * 128 + lane * 4);
    float4 a = *(const float4*)(add + (size_t)row * 128 + lane * 4);
    float v[4] = { x.x + a.x * s, x.y + a.y * s, x.z + a.z * s, x.w + a.w * s };

    float sum = v[0] + v[1] + v[2] + v[3];
#pragma unroll
    for (int off = 16; off > 0; off >>= 1) sum += __shfl_xor_sync(0xffffffffu, sum, off);
    float mean = sum * (1.0f / 128.0f);
    float sq = 0.f;
#pragma unroll
    for (int j = 0; j < 4; j++) { float d = v[j] - mean; sq += d * d; }
#pragma unroll
    for (int off = 16; off > 0; off >>= 1) sq += __shfl_xor_sync(0xffffffffu, sq, off);
    float inv = rsqrtf(sq * (1.0f / 128.0f) + 1e-5f);

    float4 gg = *(const float4*)(g + lane * 4);
    float4 bb = *(const float4*)(b + lane * 4);
    float4 o;
    o.x = (v[0] - mean) * inv * gg.x + bb.x;
    o.y = (v[1] - mean) * inv * gg.y + bb.y;
    o.z = (v[2] - mean) * inv * gg.z + bb.z;
    o.w = (v[3] - mean) * inv * gg.w + bb.w;
    *(float4*)(io + (size_t)row * 128 + lane * 4) = o;
}

// ---------------- weight transpose + tf32 + k-permute ----------------
__global__ void wt_k(float* __restrict__ dst, const float* __restrict__ src, int K, int N) {
    int i = blockIdx.x * blockDim.x + threadIdx.x;
    if (i >= K * N) return;
    int n = i / K, rem = i - n * K;
    int c = rem >> 5, p = rem & 31;
    int k = c * 32 + ((p & 7) << 2) + (p >> 3);
    dst[i] = totf32(src[(size_t)k * N + n]);
}
__global__ void copy_k(float4* __restrict__ d, const float4* __restrict__ s, int n4) {
    for (int i = blockIdx.x * blockDim.x + threadIdx.x; i < n4; i += gridDim.x * blockDim.x)
        d[i] = s[i];
}
__global__ void zero_k(float4* __restrict__ p, int n4) {
    for (int i = blockIdx.x * blockDim.x + threadIdx.x; i < n4; i += gridDim.x * blockDim.x)
        p[i] = make_float4(0.f, 0.f, 0.f, 0.f);
}
__global__ void deg_k(const int* __restrict__ dst, float* __restrict__ deg) {
    int e = blockIdx.x * blockDim.x + threadIdx.x;
    if (e < EDGES) atomicAdd(&deg[dst[e]], 1.0f);
}
__global__ void invdeg_k(float* __restrict__ deg) {
    int i = blockIdx.x * blockDim.x + threadIdx.x;
    if (i < NNODES) deg[i] = 1.0f / fmaxf(deg[i], 1.0f);
}

// ---------------- launch ----------------
extern "C" void kernel_launch(void* const* d_in, const int* in_sizes, int n_in,
                              void* d_out, int out_size)
{
    const float* x        = (const float*)d_in[0];
    const int*   eidx     = (const int*)  d_in[1];
    const float* eattr_in = (const float*)d_in[2];
    const float* msg_W0 = (const float*)d_in[3];
    const float* msg_b0 = (const float*)d_in[4];
    const float* msg_W1 = (const float*)d_in[5];
    const float* msg_b1 = (const float*)d_in[6];
    const float* msg_W2 = (const float*)d_in[7];
    const float* msg_b2 = (const float*)d_in[8];
    const float* n0g    = (const float*)d_in[9];
    const float* n0b    = (const float*)d_in[10];
    const float* ff_W0  = (const float*)d_in[11];
    const float* ff_b0  = (const float*)d_in[12];
    const float* ff_W1  = (const float*)d_in[13];
    const float* ff_b1  = (const float*)d_in[14];
    const float* n1g    = (const float*)d_in[15];
    const float* n1b    = (const float*)d_in[16];
    const float* eW0    = (const float*)d_in[17];
    const float* eb0    = (const float*)d_in[18];
    const float* eW1    = (const float*)d_in[19];
    const float* eb1    = (const float*)d_in[20];
    const float* eW2    = (const float*)d_in[21];
    const float* eb2    = (const float*)d_in[22];
    const float* eng    = (const float*)d_in[23];
    const float* enb    = (const float*)d_in[24];

    float* nodes = (float*)d_out;
    const int* src = eidx;
    const int* dst = eidx + EDGES;

    static bool init = false;
    static float *edge, *agg, *ffb, *ideg, *wt;
    if (!init) {
        cudaGetSymbolAddress((void**)&edge, g_edge);
        cudaGetSymbolAddress((void**)&agg,  g_agg);
        cudaGetSymbolAddress((void**)&ffb,  g_ff);
        cudaGetSymbolAddress((void**)&ideg, g_ideg);
        cudaGetSymbolAddress((void**)&wt,   g_wt);
        cudaFuncSetAttribute(mlp3_tc<EPI_ATOMIC>,
                             cudaFuncAttributeMaxDynamicSharedMemorySize, DYN_MLP);
        cudaFuncSetAttribute(mlp3_tc<EPI_LNRES>,
                             cudaFuncAttributeMaxDynamicSharedMemorySize, DYN_MLP);
        cudaFuncSetAttribute(gemm_tc<EPI_RELU>,
                             cudaFuncAttributeMaxDynamicSharedMemorySize, DYN_GEMM);
        cudaFuncSetAttribute(gemm_tc<EPI_LNRES>,
                             cudaFuncAttributeMaxDynamicSharedMemorySize, DYN_GEMM);
        init = true;
    }

    copy_k<<<2048, 256>>>((float4*)nodes, (const float4*)x, NNODES * DD / 4);
    copy_k<<<4096, 256>>>((float4*)edge, (const float4*)eattr_in, EDGES * DD / 4);
    zero_k<<<64, 256>>>((float4*)ideg, NNODES / 4);
    deg_k<<<EDGES / 256, 256>>>(dst, ideg);
    invdeg_k<<<NNODES / 256, 256>>>(ideg);

    const int O_MW0 = 0, O_MW1 = 49152, O_MW2 = 65536, O_FW0 = 81920,
              O_FW1 = 147456, O_EW0 = 212992, O_EW1 = 262144, O_EW2 = 278528;
    for (int l = 0; l < LAYERS; l++) {
        float* wl = wt + (size_t)l * WT_PER_LAYER;
        wt_k<<<(KCAT * DD + 255) / 256, 256>>>(wl + O_MW0, msg_W0 + (size_t)l * KCAT * DD, KCAT, DD);
        wt_k<<<(DD * DD + 255) / 256, 256>>>(wl + O_MW1, msg_W1 + (size_t)l * DD * DD, DD, DD);
        wt_k<<<(DD * DD + 255) / 256, 256>>>(wl + O_MW2, msg_W2 + (size_t)l * DD * DD, DD, DD);
        wt_k<<<(DD * FFH + 255) / 256, 256>>>(wl + O_FW0, ff_W0 + (size_t)l * DD * FFH, DD, FFH);
        wt_k<<<(FFH * DD + 255) / 256, 256>>>(wl + O_FW1, ff_W1 + (size_t)l * FFH * DD, FFH, DD);
        wt_k<<<(KCAT * DD + 255) / 256, 256>>>(wl + O_EW0, eW0 + (size_t)l * KCAT * DD, KCAT, DD);
        wt_k<<<(DD * DD + 255) / 256, 256>>>(wl + O_EW1, eW1 + (size_t)l * DD * DD, DD, DD);
        wt_k<<<(DD * DD + 255) / 256, 256>>>(wl + O_EW2, eW2 + (size_t)l * DD * DD, DD, DD);
    }

    const dim3 gE(EDGES / 128, 1), gN(NNODES / 128, 1), gF(NNODES / 128, FFH / 128);

    for (int l = 0; l < LAYERS; l++) {
        float* wl = wt + (size_t)l * WT_PER_LAYER;

        // --- fused message MLP + mean aggregation ---
        zero_k<<<4096, 256>>>((float4*)agg, NNODES * DD / 4);
        mlp3_tc<EPI_ATOMIC><<<gE, 256, DYN_MLP>>>(
            nodes, edge, src, dst,
            wl + O_MW0, msg_b0 + l * DD, wl + O_MW1, msg_b1 + l * DD,
            wl + O_MW2, msg_b2 + l * DD,
            agg, nullptr, nullptr, nullptr);
        ln_k<<<NNODES / 8, 256>>>(nodes, agg, ideg, n0g + l * DD, n0b + l * DD, NNODES);

        // --- feedforward (norm1 fused into FF2 epilogue) ---
        gemm_tc<EPI_RELU><<<gF, 256, DYN_GEMM>>>(
            nodes, DD, DD, wl + O_FW0, ff_b0 + l * FFH, ffb, FFH,
            nullptr, nullptr, nullptr);
        gemm_tc<EPI_LNRES><<<gN, 256, DYN_GEMM>>>(
            ffb, FFH, FFH, wl + O_FW1, ff_b1 + l * DD, nodes, DD,
            nodes, n1g + l * DD, n1b + l * DD);

        // --- fused edge MLP + residual LayerNorm ---
        mlp3_tc<EPI_LNRES><<<gE, 256, DYN_MLP>>>(
            nodes, edge, src, dst,
            wl + O_EW0, eb0 + l * DD, wl + O_EW1, eb1 + l * DD,
            wl + O_EW2, eb2 + l * DD,
            edge, edge, eng + l * DD, enb + l * DD);
    }
    // nodes (= d_out) holds the final [B, N, D] result.
}

// round 8
// speedup vs baseline: 2.1108x; 1.0105x over previous
#include <cuda_runtime.h>
#include <cstdint>

// ---------------- problem constants ----------------
#define EDGES   262144
#define NNODES  32768
#define DD      128
#define FFH     512
#define LAYERS  2
#define KCAT    384

#define WT_PER_LAYER 294912

// ---------------- scratch ----------------
__device__ float g_edge[EDGES * DD];
__device__ float g_agg [NNODES * DD];
__device__ float g_ff  [NNODES * FFH];
__device__ float g_ideg[NNODES];
__device__ float g_wt  [LAYERS * WT_PER_LAYER];

enum { EPI_RELU = 0, EPI_ATOMIC = 1, EPI_LNRES = 2 };

#define APITCH 36              // pitch (floats) of one 32-k operand chunk
#define HROW   146             // row stride (floats) of 4-chunk activation buf
static const int TILE_BYTES = 128 * APITCH * 4;     // 18432
static const int HA_BYTES   = 128 * HROW * 4;       // 74752
static const int DYN_MLP    = HA_BYTES + 2 * TILE_BYTES + 1024;   // 112640
static const int DYN_GEMM   = 4 * TILE_BYTES + 1024;              // 74752 (>= stage 67584)

// ---------------- device helpers ----------------
__device__ __forceinline__ float totf32(float x) {
    uint32_t t; asm("cvt.rna.tf32.f32 %0, %1;" : "=r"(t) : "f"(x));
    return __uint_as_float(t);
}
__device__ __forceinline__ void mma8(float* d, uint32_t a0, uint32_t a1,
                                     uint32_t a2, uint32_t a3,
                                     uint32_t b0, uint32_t b1) {
    asm volatile(
        "mma.sync.aligned.m16n8k8.row.col.f32.tf32.tf32.f32 "
        "{%0,%1,%2,%3}, {%4,%5,%6,%7}, {%8,%9}, {%0,%1,%2,%3};"
        : "+f"(d[0]), "+f"(d[1]), "+f"(d[2]), "+f"(d[3])
        : "r"(a0), "r"(a1), "r"(a2), "r"(a3), "r"(b0), "r"(b1));
}
__device__ __forceinline__ void chunk_mma(const float* Abase, int apitch,
                                          const float* Bs,
                                          int wm, int wn, int g, int r,
                                          float acc[2][8][4]) {
#pragma unroll
    for (int s = 0; s < 4; s++) {
        uint2 al[2], ah[2];
#pragma unroll
        for (int mt = 0; mt < 2; mt++) {
            const float* p0 = Abase + (wm + mt * 16 + g) * apitch + r * 8 + 2 * s;
            al[mt] = *(const uint2*)p0;
            ah[mt] = *(const uint2*)(p0 + 8 * apitch);
        }
        uint2 bf[8];
#pragma unroll
        for (int nt = 0; nt < 8; nt++)
            bf[nt] = *(const uint2*)(Bs + (wn + nt * 8 + g) * APITCH + r * 8 + 2 * s);
#pragma unroll
        for (int mt = 0; mt < 2; mt++)
#pragma unroll
            for (int nt = 0; nt < 8; nt++)
                mma8(acc[mt][nt], al[mt].x, ah[mt].x, al[mt].y, ah[mt].y,
                     bf[nt].x, bf[nt].y);
    }
}
// accumulators -> activation buffer (bias + relu + tf32, k-permuted); zero acc
__device__ __forceinline__ void wb_relu(float* HA, float acc[2][8][4],
                                        const float* bias,
                                        int wm, int wn, int g, int r) {
#pragma unroll
    for (int mt = 0; mt < 2; mt++)
#pragma unroll
        for (int q = 0; q < 4; q++) {
            int row = wm + mt * 16 + g + ((q & 2) ? 8 : 0);
#pragma unroll
            for (int nt = 0; nt < 8; nt++) {
                int col = wn + nt * 8 + 2 * r + (q & 1);
                float v = fmaxf(acc[mt][nt][q] + __ldg(bias + col), 0.f);
                int kk = col & 31;
                HA[row * HROW + (col >> 5) * APITCH + (kk & 3) * 8 + (kk >> 2)]
                    = totf32(v);
                acc[mt][nt][q] = 0.f;
            }
        }
}

// ---------------- fused 3-linear MLP over edges (BK=64 windows) -------------
template <int EPI>
__global__ void __launch_bounds__(256, 2)
mlp3_tc(const float* __restrict__ nodes, const float* __restrict__ eattr,
        const int* __restrict__ srcI, const int* __restrict__ dstI,
        const float* __restrict__ W0t, const float* __restrict__ b0,
        const float* __restrict__ W1t, const float* __restrict__ b1,
        const float* __restrict__ W2t, const float* __restrict__ b2,
        float* __restrict__ out, const float* __restrict__ resid,
        const float* __restrict__ lng, const float* __restrict__ lnb)
{
    extern __shared__ char dyn[];
    char*  basep = (char*)(((uintptr_t)dyn + 1023) & ~(uintptr_t)1023);
    float* HA    = (float*)basep;                       // [128][HROW]
    float* Bs0   = (float*)(basep + HA_BYTES);
    float* Bs1   = (float*)(basep + HA_BYTES + TILE_BYTES);
    float* stage = HA;                                  // reuse, pitch 132

    __shared__ int s_src[128], s_dst[128];

    const int tid  = threadIdx.x;
    const int wid  = tid >> 5;
    const int lane = tid & 31;
    const int g    = lane >> 2;
    const int r    = lane & 3;
    const int wm   = (wid & 3) * 32;
    const int wn   = (wid >> 2) * 64;
    const int m0   = blockIdx.x * 128;

    if (tid < 128) { s_src[tid] = srcI[m0 + tid]; s_dst[tid] = dstI[m0 + tid]; }
    __syncthreads();

    float acc[2][8][4];
#pragma unroll
    for (int mt = 0; mt < 2; mt++)
#pragma unroll
        for (int nt = 0; nt < 8; nt++)
#pragma unroll
            for (int q = 0; q < 4; q++) acc[mt][nt][q] = 0.f;

    int arow[4], acol[4];
#pragma unroll
    for (int i = 0; i < 4; i++) {
        int f4 = tid + i * 256;
        arow[i] = f4 >> 3;
        acol[i] = f4 & 7;
    }

    // gather one 32-k chunk of the concat into HA slot (c&3)
    auto loadA = [&](int c) {
        int k0 = c * 32;
        float* slot = HA + (c & 3) * APITCH;
#pragma unroll
        for (int i = 0; i < 4; i++) {
            const float* ap;
            if (k0 < 128)      ap = nodes + (size_t)s_src[arow[i]] * 128 + k0 + acol[i] * 4;
            else if (k0 < 256) ap = eattr + (size_t)(m0 + arow[i]) * 128 + (k0 - 128) + acol[i] * 4;
            else               ap = nodes + (size_t)s_dst[arow[i]] * 128 + (k0 - 256) + acol[i] * 4;
            float4 v = *(const float4*)ap;
            float* arp = slot + arow[i] * HROW;
            arp[ 0 + acol[i]] = totf32(v.x);
            arp[ 8 + acol[i]] = totf32(v.y);
            arp[16 + acol[i]] = totf32(v.z);
            arp[24 + acol[i]] = totf32(v.w);
        }
    };
    auto loadB = [&](const float* Wt, int Kdim, int c, float* Bbuf) {
#pragma unroll
        for (int i = 0; i < 4; i++)
            *(float4*)(Bbuf + arow[i] * APITCH + acol[i] * 4) =
                *(const float4*)(Wt + (size_t)arow[i] * Kdim + c * 32 + acol[i] * 4);
    };

    // ---- stage 0: K = 384, two 32-k chunks per sync window ----
    for (int c = 0; c < 12; c += 2) {
        loadA(c);
        loadA(c + 1);
        loadB(W0t, KCAT, c, Bs0);
        loadB(W0t, KCAT, c + 1, Bs1);
        __syncthreads();
        chunk_mma(HA + (c & 3) * APITCH, HROW, Bs0, wm, wn, g, r, acc);
        chunk_mma(HA + ((c + 1) & 3) * APITCH, HROW, Bs1, wm, wn, g, r, acc);
        __syncthreads();
    }
    wb_relu(HA, acc, b0, wm, wn, g, r);
    __syncthreads();

    // ---- stage 1: K = 128, A resident in HA ----
    for (int c = 0; c < 4; c += 2) {
        loadB(W1t, 128, c, Bs0);
        loadB(W1t, 128, c + 1, Bs1);
        __syncthreads();
        chunk_mma(HA + c * APITCH, HROW, Bs0, wm, wn, g, r, acc);
        chunk_mma(HA + (c + 1) * APITCH, HROW, Bs1, wm, wn, g, r, acc);
        __syncthreads();
    }
    wb_relu(HA, acc, b1, wm, wn, g, r);
    __syncthreads();

    // ---- stage 2: K = 128 ----
    for (int c = 0; c < 4; c += 2) {
        loadB(W2t, 128, c, Bs0);
        loadB(W2t, 128, c + 1, Bs1);
        __syncthreads();
        chunk_mma(HA + c * APITCH, HROW, Bs0, wm, wn, g, r, acc);
        chunk_mma(HA + (c + 1) * APITCH, HROW, Bs1, wm, wn, g, r, acc);
        __syncthreads();
    }

    // ---- epilogue ----
    if (EPI == EPI_ATOMIC) {
#pragma unroll
        for (int mt = 0; mt < 2; mt++)
#pragma unroll
            for (int q = 0; q < 4; q++) {
                int row = wm + mt * 16 + g + ((q & 2) ? 8 : 0);
#pragma unroll
                for (int nt = 0; nt < 8; nt++) {
                    int col = wn + nt * 8 + 2 * r + (q & 1);
                    stage[row * 132 + col] = acc[mt][nt][q] + __ldg(b2 + col);
                }
            }
        __syncthreads();
#pragma unroll
        for (int it = 0; it < 16; it++) {
            int f4  = it * 256 + tid;
            int row = f4 >> 5;
            int c4  = f4 & 31;
            float4 v = *(float4*)(stage + row * 132 + c4 * 4);
            float* dbase = out + (size_t)s_dst[row] * 128 + c4 * 4;
            asm volatile("red.global.add.v4.f32 [%0], {%1,%2,%3,%4};"
                         :: "l"(dbase), "f"(v.x), "f"(v.y), "f"(v.z), "f"(v.w)
                         : "memory");
        }
    } else {  // EPI_LNRES: out = LN(resid + acc + b2)
#pragma unroll
        for (int mt = 0; mt < 2; mt++)
#pragma unroll
            for (int q = 0; q < 4; q++) {
                int row = wm + mt * 16 + g + ((q & 2) ? 8 : 0);
#pragma unroll
                for (int nt = 0; nt < 8; nt++) {
                    int col = wn + nt * 8 + 2 * r + (q & 1);
                    stage[row * 132 + col] = acc[mt][nt][q];
                }
            }
        __syncthreads();
        float4 gg  = *(const float4*)(lng + lane * 4);
        float4 bbn = *(const float4*)(lnb + lane * 4);
        float4 bz  = *(const float4*)(b2 + lane * 4);
        for (int rr = wid; rr < 128; rr += 8) {
            float4 res = *(const float4*)(resid + (size_t)(m0 + rr) * 128 + lane * 4);
            float4 d   = *(float4*)(stage + rr * 132 + lane * 4);
            float v0 = res.x + d.x + bz.x, v1 = res.y + d.y + bz.y;
            float v2 = res.z + d.z + bz.z, v3 = res.w + d.w + bz.w;
            float sum = v0 + v1 + v2 + v3;
#pragma unroll
            for (int off = 16; off > 0; off >>= 1)
                sum += __shfl_xor_sync(0xffffffffu, sum, off);
            float mean = sum * (1.0f / 128.0f);
            float d0 = v0 - mean, d1 = v1 - mean, d2 = v2 - mean, d3 = v3 - mean;
            float sq = d0 * d0 + d1 * d1 + d2 * d2 + d3 * d3;
#pragma unroll
            for (int off = 16; off > 0; off >>= 1)
                sq += __shfl_xor_sync(0xffffffffu, sq, off);
            float inv = rsqrtf(sq * (1.0f / 128.0f) + 1e-5f);
            float4 o;
            o.x = d0 * inv * gg.x + bbn.x;
            o.y = d1 * inv * gg.y + bbn.y;
            o.z = d2 * inv * gg.z + bbn.z;
            o.w = d3 * inv * gg.w + bbn.w;
            *(float4*)(out + (size_t)(m0 + rr) * 128 + lane * 4) = o;
        }
    }
}

// ---------------- dense GEMM (feedforward), BK=64 windows ----------------
template <int EPI>
__global__ void __launch_bounds__(256, 2)
gemm_tc(const float* __restrict__ A, int lda, int K,
        const float* __restrict__ Wt, const float* __restrict__ bias,
        float* __restrict__ out, int ldo,
        const float* __restrict__ resid,
        const float* __restrict__ lng, const float* __restrict__ lnb)
{
    extern __shared__ char dyn[];
    char*  base  = (char*)(((uintptr_t)dyn + 1023) & ~(uintptr_t)1023);
    float* As0   = (float*)base;
    float* As1   = (float*)(base + TILE_BYTES);
    float* Bs0   = (float*)(base + 2 * TILE_BYTES);
    float* Bs1   = (float*)(base + 3 * TILE_BYTES);
    float* stage = (float*)base;

    const int tid  = threadIdx.x;
    const int wid  = tid >> 5;
    const int lane = tid & 31;
    const int g    = lane >> 2;
    const int r    = lane & 3;
    const int wm   = (wid & 3) * 32;
    const int wn   = (wid >> 2) * 64;
    const int m0   = blockIdx.x * 128;
    const int n0   = blockIdx.y * 128;

    float acc[2][8][4];
#pragma unroll
    for (int mt = 0; mt < 2; mt++)
#pragma unroll
        for (int nt = 0; nt < 8; nt++)
#pragma unroll
            for (int q = 0; q < 4; q++) acc[mt][nt][q] = 0.f;

    int arow[4], acol[4];
#pragma unroll
    for (int i = 0; i < 4; i++) {
        int f4 = tid + i * 256;
        arow[i] = f4 >> 3;
        acol[i] = f4 & 7;
    }

    auto loadA = [&](int c, float* Abuf) {
#pragma unroll
        for (int i = 0; i < 4; i++) {
            float4 v = *(const float4*)(A + (size_t)(m0 + arow[i]) * lda + c * 32 + acol[i] * 4);
            float* arp = Abuf + arow[i] * APITCH;
            arp[ 0 + acol[i]] = totf32(v.x);
            arp[ 8 + acol[i]] = totf32(v.y);
            arp[16 + acol[i]] = totf32(v.z);
            arp[24 + acol[i]] = totf32(v.w);
        }
    };
    auto loadB = [&](int c, float* Bbuf) {
#pragma unroll
        for (int i = 0; i < 4; i++)
            *(float4*)(Bbuf + arow[i] * APITCH + acol[i] * 4) =
                *(const float4*)(Wt + (size_t)(n0 + arow[i]) * K + c * 32 + acol[i] * 4);
    };

    const int NC = K >> 5;   // always even here (4 or 16)
    for (int c = 0; c < NC; c += 2) {
        loadA(c, As0);
        loadA(c + 1, As1);
        loadB(c, Bs0);
        loadB(c + 1, Bs1);
        __syncthreads();
        chunk_mma(As0, APITCH, Bs0, wm, wn, g, r, acc);
        chunk_mma(As1, APITCH, Bs1, wm, wn, g, r, acc);
        __syncthreads();
    }

#pragma unroll
    for (int mt = 0; mt < 2; mt++) {
        int rw0 = wm + mt * 16 + g;
#pragma unroll
        for (int nt = 0; nt < 8; nt++) {
            int col = wn + nt * 8 + 2 * r;
            *(float2*)(stage + rw0 * 132 + col)       = make_float2(acc[mt][nt][0], acc[mt][nt][1]);
            *(float2*)(stage + (rw0 + 8) * 132 + col) = make_float2(acc[mt][nt][2], acc[mt][nt][3]);
        }
    }
    __syncthreads();

    if (EPI == EPI_RELU) {
#pragma unroll
        for (int it = 0; it < 16; it++) {
            int f4  = it * 256 + tid;
            int row = f4 >> 5;
            int c4  = f4 & 31;
            float4 v  = *(float4*)(stage + row * 132 + c4 * 4);
            float4 bb = *(const float4*)(bias + n0 + c4 * 4);
            v.x = fmaxf(v.x + bb.x, 0.f); v.y = fmaxf(v.y + bb.y, 0.f);
            v.z = fmaxf(v.z + bb.z, 0.f); v.w = fmaxf(v.w + bb.w, 0.f);
            *(float4*)(out + (size_t)(m0 + row) * ldo + n0 + c4 * 4) = v;
        }
    } else {  // EPI_LNRES
        float4 gg  = *(const float4*)(lng + lane * 4);
        float4 bbn = *(const float4*)(lnb + lane * 4);
        float4 bz  = *(const float4*)(bias + lane * 4);
        for (int rr = wid; rr < 128; rr += 8) {
            float4 res = *(const float4*)(resid + (size_t)(m0 + rr) * 128 + lane * 4);
            float4 d   = *(float4*)(stage + rr * 132 + lane * 4);
            float v0 = res.x + d.x + bz.x, v1 = res.y + d.y + bz.y;
            float v2 = res.z + d.z + bz.z, v3 = res.w + d.w + bz.w;
            float sum = v0 + v1 + v2 + v3;
#pragma unroll
            for (int off = 16; off > 0; off >>= 1)
                sum += __shfl_xor_sync(0xffffffffu, sum, off);
            float mean = sum * (1.0f / 128.0f);
            float d0 = v0 - mean, d1 = v1 - mean, d2 = v2 - mean, d3 = v3 - mean;
            float sq = d0 * d0 + d1 * d1 + d2 * d2 + d3 * d3;
#pragma unroll
            for (int off = 16; off > 0; off >>= 1)
                sq += __shfl_xor_sync(0xffffffffu, sq, off);
            float inv = rsqrtf(sq * (1.0f / 128.0f) + 1e-5f);
            float4 o;
            o.x = d0 * inv * gg.x + bbn.x;
            o.y = d1 * inv * gg.y + bbn.y;
            o.z = d2 * inv * gg.z + bbn.z;
            o.w = d3 * inv * gg.w + bbn.w;
            *(float4*)(out + (size_t)(m0 + rr) * 128 + lane * 4) = o;
        }
    }
}

// ---------------- standalone LayerNorm (norm0) ----------------
__global__ void ln_k(float* __restrict__ io, const float* __restrict__ add,
                     const float* __restrict__ scale,
                     const float* __restrict__ g, const float* __restrict__ b,
                     int rows)
{
    int row  = blockIdx.x * 8 + (threadIdx.x >> 5);
    int lane = threadIdx.x & 31;
    if (row >= rows) return;
    float s = scale ? scale[row] : 1.0f;

    float4 x = *(const float4*)(io  + (size_t)row * 128 + lane * 4);
    float4 a = *(const float4*)(add + (size_t)row * 128 + lane * 4);
    float v[4] = { x.x + a.x * s, x.y + a.y * s, x.z + a.z * s, x.w + a.w * s };

    float sum = v[0] + v[1] + v[2] + v[3];
#pragma unroll
    for (int off = 16; off > 0; off >>= 1) sum += __shfl_xor_sync(0xffffffffu, sum, off);
    float mean = sum * (1.0f / 128.0f);
    float sq = 0.f;
#pragma unroll
    for (int j = 0; j < 4; j++) { float d = v[j] - mean; sq += d * d; }
#pragma unroll
    for (int off = 16; off > 0; off >>= 1) sq += __shfl_xor_sync(0xffffffffu, sq, off);
    float inv = rsqrtf(sq * (1.0f / 128.0f) + 1e-5f);

    float4 gg = *(const float4*)(g + lane * 4);
    float4 bb = *(const float4*)(b + lane * 4);
    float4 o;
    o.x = (v[0] - mean) * inv * gg.x + bb.x;
    o.y = (v[1] - mean) * inv * gg.y + bb.y;
    o.z = (v[2] - mean) * inv * gg.z + bb.z;
    o.w = (v[3] - mean) * inv * gg.w + bb.w;
    *(float4*)(io + (size_t)row * 128 + lane * 4) = o;
}

// ---------------- weight transpose + tf32 + k-permute ----------------
__global__ void wt_k(float* __restrict__ dst, const float* __restrict__ src, int K, int N) {
    int i = blockIdx.x * blockDim.x + threadIdx.x;
    if (i >= K * N) return;
    int n = i / K, rem = i - n * K;
    int c = rem >> 5, p = rem & 31;
    int k = c * 32 + ((p & 7) << 2) + (p >> 3);
    dst[i] = totf32(src[(size_t)k * N + n]);
}
__global__ void copy_k(float4* __restrict__ d, const float4* __restrict__ s, int n4) {
    for (int i = blockIdx.x * blockDim.x + threadIdx.x; i < n4; i += gridDim.x * blockDim.x)
        d[i] = s[i];
}
__global__ void zero_k(float4* __restrict__ p, int n4) {
    for (int i = blockIdx.x * blockDim.x + threadIdx.x; i < n4; i += gridDim.x * blockDim.x)
        p[i] = make_float4(0.f, 0.f, 0.f, 0.f);
}
__global__ void deg_k(const int* __restrict__ dst, float* __restrict__ deg) {
    int e = blockIdx.x * blockDim.x + threadIdx.x;
    if (e < EDGES) atomicAdd(&deg[dst[e]], 1.0f);
}
__global__ void invdeg_k(float* __restrict__ deg) {
    int i = blockIdx.x * blockDim.x + threadIdx.x;
    if (i < NNODES) deg[i] = 1.0f / fmaxf(deg[i], 1.0f);
}

// ---------------- launch ----------------
extern "C" void kernel_launch(void* const* d_in, const int* in_sizes, int n_in,
                              void* d_out, int out_size)
{
    const float* x        = (const float*)d_in[0];
    const int*   eidx     = (const int*)  d_in[1];
    const float* eattr_in = (const float*)d_in[2];
    const float* msg_W0 = (const float*)d_in[3];
    const float* msg_b0 = (const float*)d_in[4];
    const float* msg_W1 = (const float*)d_in[5];
    const float* msg_b1 = (const float*)d_in[6];
    const float* msg_W2 = (const float*)d_in[7];
    const float* msg_b2 = (const float*)d_in[8];
    const float* n0g    = (const float*)d_in[9];
    const float* n0b    = (const float*)d_in[10];
    const float* ff_W0  = (const float*)d_in[11];
    const float* ff_b0  = (const float*)d_in[12];
    const float* ff_W1  = (const float*)d_in[13];
    const float* ff_b1  = (const float*)d_in[14];
    const float* n1g    = (const float*)d_in[15];
    const float* n1b    = (const float*)d_in[16];
    const float* eW0    = (const float*)d_in[17];
    const float* eb0    = (const float*)d_in[18];
    const float* eW1    = (const float*)d_in[19];
    const float* eb1    = (const float*)d_in[20];
    const float* eW2    = (const float*)d_in[21];
    const float* eb2    = (const float*)d_in[22];
    const float* eng    = (const float*)d_in[23];
    const float* enb    = (const float*)d_in[24];

    float* nodes = (float*)d_out;
    const int* src = eidx;
    const int* dst = eidx + EDGES;

    static bool init = false;
    static float *edge, *agg, *ffb, *ideg, *wt;
    if (!init) {
        cudaGetSymbolAddress((void**)&edge, g_edge);
        cudaGetSymbolAddress((void**)&agg,  g_agg);
        cudaGetSymbolAddress((void**)&ffb,  g_ff);
        cudaGetSymbolAddress((void**)&ideg, g_ideg);
        cudaGetSymbolAddress((void**)&wt,   g_wt);
        cudaFuncSetAttribute(mlp3_tc<EPI_ATOMIC>,
                             cudaFuncAttributeMaxDynamicSharedMemorySize, DYN_MLP);
        cudaFuncSetAttribute(mlp3_tc<EPI_LNRES>,
                             cudaFuncAttributeMaxDynamicSharedMemorySize, DYN_MLP);
        cudaFuncSetAttribute(gemm_tc<EPI_RELU>,
                             cudaFuncAttributeMaxDynamicSharedMemorySize, DYN_GEMM);
        cudaFuncSetAttribute(gemm_tc<EPI_LNRES>,
                             cudaFuncAttributeMaxDynamicSharedMemorySize, DYN_GEMM);
        init = true;
    }

    copy_k<<<2048, 256>>>((float4*)nodes, (const float4*)x, NNODES * DD / 4);
    copy_k<<<4096, 256>>>((float4*)edge, (const float4*)eattr_in, EDGES * DD / 4);
    zero_k<<<64, 256>>>((float4*)ideg, NNODES / 4);
    deg_k<<<EDGES / 256, 256>>>(dst, ideg);
    invdeg_k<<<NNODES / 256, 256>>>(ideg);

    const int O_MW0 = 0, O_MW1 = 49152, O_MW2 = 65536, O_FW0 = 81920,
              O_FW1 = 147456, O_EW0 = 212992, O_EW1 = 262144, O_EW2 = 278528;
    for (int l = 0; l < LAYERS; l++) {
        float* wl = wt + (size_t)l * WT_PER_LAYER;
        wt_k<<<(KCAT * DD + 255) / 256, 256>>>(wl + O_MW0, msg_W0 + (size_t)l * KCAT * DD, KCAT, DD);
        wt_k<<<(DD * DD + 255) / 256, 256>>>(wl + O_MW1, msg_W1 + (size_t)l * DD * DD, DD, DD);
        wt_k<<<(DD * DD + 255) / 256, 256>>>(wl + O_MW2, msg_W2 + (size_t)l * DD * DD, DD, DD);
        wt_k<<<(DD * FFH + 255) / 256, 256>>>(wl + O_FW0, ff_W0 + (size_t)l * DD * FFH, DD, FFH);
        wt_k<<<(FFH * DD + 255) / 256, 256>>>(wl + O_FW1, ff_W1 + (size_t)l * FFH * DD, FFH, DD);
        wt_k<<<(KCAT * DD + 255) / 256, 256>>>(wl + O_EW0, eW0 + (size_t)l * KCAT * DD, KCAT, DD);
        wt_k<<<(DD * DD + 255) / 256, 256>>>(wl + O_EW1, eW1 + (size_t)l * DD * DD, DD, DD);
        wt_k<<<(DD * DD + 255) / 256, 256>>>(wl + O_EW2, eW2 + (size_t)l * DD * DD, DD, DD);
    }

    const dim3 gE(EDGES / 128, 1), gN(NNODES / 128, 1), gF(NNODES / 128, FFH / 128);

    for (int l = 0; l < LAYERS; l++) {
        float* wl = wt + (size_t)l * WT_PER_LAYER;

        // --- fused message MLP + mean aggregation ---
        zero_k<<<4096, 256>>>((float4*)agg, NNODES * DD / 4);
        mlp3_tc<EPI_ATOMIC><<<gE, 256, DYN_MLP>>>(
            nodes, edge, src, dst,
            wl + O_MW0, msg_b0 + l * DD, wl + O_MW1, msg_b1 + l * DD,
            wl + O_MW2, msg_b2 + l * DD,
            agg, nullptr, nullptr, nullptr);
        ln_k<<<NNODES / 8, 256>>>(nodes, agg, ideg, n0g + l * DD, n0b + l * DD, NNODES);

        // --- feedforward (norm1 fused into FF2 epilogue) ---
        gemm_tc<EPI_RELU><<<gF, 256, DYN_GEMM>>>(
            nodes, DD, DD, wl + O_FW0, ff_b0 + l * FFH, ffb, FFH,
            nullptr, nullptr, nullptr);
        gemm_tc<EPI_LNRES><<<gN, 256, DYN_GEMM>>>(
            ffb, FFH, FFH, wl + O_FW1, ff_b1 + l * DD, nodes, DD,
            nodes, n1g + l * DD, n1b + l * DD);

        // --- fused edge MLP + residual LayerNorm ---
        mlp3_tc<EPI_LNRES><<<gE, 256, DYN_MLP>>>(
            nodes, edge, src, dst,
            wl + O_EW0, eb0 + l * DD, wl + O_EW1, eb1 + l * DD,
            wl + O_EW2, eb2 + l * DD,
            edge, edge, eng + l * DD, enb + l * DD);
    }
    // nodes (= d_out) holds the final [B, N, D] result.
}